// round 1
// baseline (speedup 1.0000x reference)
#include <cuda_runtime.h>

#define BB 32
#define NN 16384
#define DD 64

// ---------------- pass 1 (ctx = softmax(k)^T @ v) ----------------
#define P1_CHUNKS 16
#define P1_CROWS (NN / P1_CHUNKS)    // 1024 rows per block
#define P1_TROWS 32                  // rows per smem tile
#define P1_NT (P1_CROWS / P1_TROWS)  // 32 tiles
#define KST 68                       // padded tile row stride (floats, 16B-mult)
#define SST 68                       // stage row stride

// ---------------- pass 2 (out = softmax(q) @ ctx) ----------------
#define P2_CHUNKS 16
#define P2_CROWS (NN / P2_CHUNKS)    // 1024 rows per block
#define P2_TROWS 64                  // rows per tile
#define P2_NT (P2_CROWS / P2_TROWS)  // 16 tiles
#define QST 68                       // qt row stride (floats)

__device__ float g_ctx[BB * DD * DD];   // 512 KB scratch

// packed fp32x2 FMA (2x fp32 throughput vs scalar FFMA on sm_103a)
__device__ __forceinline__ float2 ffma2(float2 a, float2 b, float2 c) {
    union U { float2 f; unsigned long long u; };
    U A, B2, C, R;
    A.f = a; B2.f = b; C.f = c;
    asm("fma.rn.f32x2 %0, %1, %2, %3;"
        : "=l"(R.u) : "l"(A.u), "l"(B2.u), "l"(C.u));
    return R.f;
}

// softmax over 8 local values replicated across an 8-lane group (lanes share row)
__device__ __forceinline__ void softmax8(float4 a, float4 b, float* o) {
    float m = fmaxf(fmaxf(fmaxf(a.x, a.y), fmaxf(a.z, a.w)),
                    fmaxf(fmaxf(b.x, b.y), fmaxf(b.z, b.w)));
    m = fmaxf(m, __shfl_xor_sync(0xffffffffu, m, 1));
    m = fmaxf(m, __shfl_xor_sync(0xffffffffu, m, 2));
    m = fmaxf(m, __shfl_xor_sync(0xffffffffu, m, 4));
    o[0] = __expf(a.x - m); o[1] = __expf(a.y - m);
    o[2] = __expf(a.z - m); o[3] = __expf(a.w - m);
    o[4] = __expf(b.x - m); o[5] = __expf(b.y - m);
    o[6] = __expf(b.z - m); o[7] = __expf(b.w - m);
    float s = o[0] + o[1] + o[2] + o[3] + o[4] + o[5] + o[6] + o[7];
    s += __shfl_xor_sync(0xffffffffu, s, 1);
    s += __shfl_xor_sync(0xffffffffu, s, 2);
    s += __shfl_xor_sync(0xffffffffu, s, 4);
    float inv = __frcp_rn(s);
#pragma unroll
    for (int i = 0; i < 8; i++) o[i] *= inv;
}

__global__ void zero_ctx_kernel() {
    int i = blockIdx.x * blockDim.x + threadIdx.x;
    if (i < BB * DD * DD) g_ctx[i] = 0.f;
}

// ============================ PASS 1 ============================
// grid (P1_CHUNKS, BB), 256 threads. Each warp owns the full 64x64 ctx
// as an 8x16 per-lane register tile, over its subset of rows.
__global__ void __launch_bounds__(256, 1) ctx_kernel(
    const float* __restrict__ K, const float* __restrict__ V)
{
    extern __shared__ float sm[];
    float* kn    = sm;                         // [P1_TROWS][KST]  softmaxed k
    float* vv    = sm + P1_TROWS * KST;        // [P1_TROWS][KST]  raw v
    float* stage = vv + P1_TROWS * KST;        // [8][DD][SST]     warp partials

    const int b  = blockIdx.y;
    const int n0 = blockIdx.x * P1_CROWS;

    const int tid  = threadIdx.x;
    const int wid  = tid >> 5;
    const int lane = tid & 31;

    // load/softmax mapping: 8 lanes per row, 4 rows per warp
    const int lrow = lane >> 3;          // 0..3
    const int lcol = (lane & 7) << 3;    // 0,8,...,56

    // accumulate mapping: lane -> (d-octet, e-16-group)
    const int ti = lane >> 2;            // 0..7  -> d = 8*ti ..
    const int tj = lane & 3;             // 0..3  -> e = 16*tj ..

    const float* Kb = K + ((size_t)b * NN) * DD;
    const float* Vb = V + ((size_t)b * NN) * DD;

    float2 acc[8][8];
#pragma unroll
    for (int i = 0; i < 8; i++)
#pragma unroll
        for (int j = 0; j < 8; j++) acc[i][j] = make_float2(0.f, 0.f);

    // prefetch tile 0
    const float* kp = Kb + (size_t)(n0 + (wid << 2) + lrow) * DD + lcol;
    const float* vp = Vb + (size_t)(n0 + (wid << 2) + lrow) * DD + lcol;
    float4 k0 = *(const float4*)kp;
    float4 k1 = *(const float4*)(kp + 4);
    float4 v0 = *(const float4*)vp;
    float4 v1 = *(const float4*)(vp + 4);

    for (int it = 0; it < P1_NT; ++it) {
        // softmax k segment in registers, store tile to smem
        float o[8];
        softmax8(k0, k1, o);
        const int srow = (wid << 2) + lrow;
        float* kd = kn + srow * KST + lcol;
        ((float4*)kd)[0] = make_float4(o[0], o[1], o[2], o[3]);
        ((float4*)kd)[1] = make_float4(o[4], o[5], o[6], o[7]);
        float* vd = vv + srow * KST + lcol;
        ((float4*)vd)[0] = v0;
        ((float4*)vd)[1] = v1;
        __syncthreads();

        // prefetch next tile (overlaps FMA phase below)
        if (it + 1 < P1_NT) {
            const float* kp2 = Kb + (size_t)(n0 + (it + 1) * P1_TROWS + (wid << 2) + lrow) * DD + lcol;
            const float* vp2 = Vb + (size_t)(n0 + (it + 1) * P1_TROWS + (wid << 2) + lrow) * DD + lcol;
            k0 = *(const float4*)kp2;
            k1 = *(const float4*)(kp2 + 4);
            v0 = *(const float4*)vp2;
            v1 = *(const float4*)(vp2 + 4);
        }

        // accumulate: warp w handles rows {w, w+8, w+16, w+24}
#pragma unroll
        for (int rr = 0; rr < 4; ++rr) {
            const int r = wid + (rr << 3);
            const float* kr = kn + r * KST + (ti << 3);
            const float* vr = vv + r * KST + (tj << 4);
            float4 ka  = ((const float4*)kr)[0];
            float4 kb4 = ((const float4*)kr)[1];
            float4 va  = ((const float4*)vr)[0];
            float4 vb4 = ((const float4*)vr)[1];
            float4 vc  = ((const float4*)vr)[2];
            float4 vd4 = ((const float4*)vr)[3];
            float kk[8] = {ka.x, ka.y, ka.z, ka.w, kb4.x, kb4.y, kb4.z, kb4.w};
            float2 vv2[8] = {
                make_float2(va.x, va.y),  make_float2(va.z, va.w),
                make_float2(vb4.x, vb4.y), make_float2(vb4.z, vb4.w),
                make_float2(vc.x, vc.y),  make_float2(vc.z, vc.w),
                make_float2(vd4.x, vd4.y), make_float2(vd4.z, vd4.w)};
#pragma unroll
            for (int i = 0; i < 8; i++) {
                float2 kd2 = make_float2(kk[i], kk[i]);
#pragma unroll
                for (int j = 0; j < 8; j++)
                    acc[i][j] = ffma2(kd2, vv2[j], acc[i][j]);
            }
        }
        __syncthreads();
    }

    // stage warp partials to smem
    float* st = stage + wid * (DD * SST);
#pragma unroll
    for (int i = 0; i < 8; i++) {
        const int d = (ti << 3) + i;
#pragma unroll
        for (int j = 0; j < 8; j++) {
            const int e = (tj << 4) + (j << 1);
            *(float2*)(st + d * SST + e) = acc[i][j];
        }
    }
    __syncthreads();

    // reduce 8 partials -> atomicAdd into g_ctx
    const int d  = tid >> 2;
    const int e0 = (tid & 3) << 4;
    float4 r0 = make_float4(0, 0, 0, 0), r1 = r0, r2 = r0, r3 = r0;
#pragma unroll
    for (int w = 0; w < 8; w++) {
        const float4* p = (const float4*)(stage + (w * DD + d) * SST + e0);
        float4 a0 = p[0], a1 = p[1], a2 = p[2], a3 = p[3];
        r0.x += a0.x; r0.y += a0.y; r0.z += a0.z; r0.w += a0.w;
        r1.x += a1.x; r1.y += a1.y; r1.z += a1.z; r1.w += a1.w;
        r2.x += a2.x; r2.y += a2.y; r2.z += a2.z; r2.w += a2.w;
        r3.x += a3.x; r3.y += a3.y; r3.z += a3.z; r3.w += a3.w;
    }
    float* dst = g_ctx + b * DD * DD + d * DD + e0;
    atomicAdd(dst + 0,  r0.x); atomicAdd(dst + 1,  r0.y);
    atomicAdd(dst + 2,  r0.z); atomicAdd(dst + 3,  r0.w);
    atomicAdd(dst + 4,  r1.x); atomicAdd(dst + 5,  r1.y);
    atomicAdd(dst + 6,  r1.z); atomicAdd(dst + 7,  r1.w);
    atomicAdd(dst + 8,  r2.x); atomicAdd(dst + 9,  r2.y);
    atomicAdd(dst + 10, r2.z); atomicAdd(dst + 11, r2.w);
    atomicAdd(dst + 12, r3.x); atomicAdd(dst + 13, r3.y);
    atomicAdd(dst + 14, r3.z); atomicAdd(dst + 15, r3.w);
}

// ============================ PASS 2 ============================
// grid (P2_CHUNKS, BB), 256 threads. ctx in smem; q softmaxed in regs,
// stored transposed qt[d][row] so the d-loop is shuffle-free float4 reads.
__global__ void __launch_bounds__(256, 2) out_kernel(
    const float* __restrict__ Q, float* __restrict__ OUT)
{
    __shared__ float sctx[DD * DD];       // [d][e]
    __shared__ float qt[DD][QST];         // [d][row(64)+pad]

    const int b  = blockIdx.y;
    const int n0 = blockIdx.x * P2_CROWS;

    const int tid  = threadIdx.x;
    const int wid  = tid >> 5;
    const int lane = tid & 31;
    const int lrow = lane >> 3;
    const int lcol = (lane & 7) << 3;

    const float* Qb = Q + ((size_t)b * NN) * DD;
    float* Ob       = OUT + ((size_t)b * NN) * DD;

    {   // load ctx (visible after first __syncthreads below)
        const float4* src = (const float4*)(g_ctx + b * DD * DD);
        float4* dst = (float4*)sctx;
        for (int i = tid; i < (DD * DD) / 4; i += 256) dst[i] = src[i];
    }

    // prefetch tile 0: each warp loads 8 rows (two 4-row sub-batches)
    const float* qp0 = Qb + (size_t)(n0 + (wid << 3) + lrow) * DD + lcol;
    float4 qa0 = *(const float4*)qp0;
    float4 qb0 = *(const float4*)(qp0 + 4);
    float4 qa1 = *(const float4*)(qp0 + 4 * DD);
    float4 qb1 = *(const float4*)(qp0 + 4 * DD + 4);

    for (int it = 0; it < P2_NT; ++it) {
        __syncthreads();  // prev-iter FMA reads of qt done (no-op cost at it=0)

        float o[8];
        const int srow = (wid << 3) + lrow;
        softmax8(qa0, qb0, o);
#pragma unroll
        for (int i = 0; i < 8; i++) qt[lcol + i][srow] = o[i];
        softmax8(qa1, qb1, o);
#pragma unroll
        for (int i = 0; i < 8; i++) qt[lcol + i][srow + 4] = o[i];
        __syncthreads();

        // prefetch next tile (overlaps FMA phase)
        if (it + 1 < P2_NT) {
            const float* qp = Qb + (size_t)(n0 + (it + 1) * P2_TROWS + (wid << 3) + lrow) * DD + lcol;
            qa0 = *(const float4*)qp;
            qb0 = *(const float4*)(qp + 4);
            qa1 = *(const float4*)(qp + 4 * DD);
            qb1 = *(const float4*)(qp + 4 * DD + 4);
        }

        // warp 'wid' computes rows [8*wid, 8*wid+8) x all 64 e; lane owns e={2*lane,2*lane+1}
        float2 acc[4][2];
#pragma unroll
        for (int rp = 0; rp < 4; rp++) {
            acc[rp][0] = make_float2(0.f, 0.f);
            acc[rp][1] = make_float2(0.f, 0.f);
        }

        const float* qbase = &qt[0][wid << 3];
        const float* cbase = sctx + (lane << 1);
#pragma unroll 16
        for (int d = 0; d < DD; ++d) {
            float4 qA = *(const float4*)(qbase + d * QST);
            float4 qB = *(const float4*)(qbase + d * QST + 4);
            float2 c  = *(const float2*)(cbase + d * DD);
            float2 cx = make_float2(c.x, c.x);
            float2 cy = make_float2(c.y, c.y);
            float2 q01 = make_float2(qA.x, qA.y);
            float2 q23 = make_float2(qA.z, qA.w);
            float2 q45 = make_float2(qB.x, qB.y);
            float2 q67 = make_float2(qB.z, qB.w);
            acc[0][0] = ffma2(q01, cx, acc[0][0]);
            acc[0][1] = ffma2(q01, cy, acc[0][1]);
            acc[1][0] = ffma2(q23, cx, acc[1][0]);
            acc[1][1] = ffma2(q23, cy, acc[1][1]);
            acc[2][0] = ffma2(q45, cx, acc[2][0]);
            acc[2][1] = ffma2(q45, cy, acc[2][1]);
            acc[3][0] = ffma2(q67, cx, acc[3][0]);
            acc[3][1] = ffma2(q67, cy, acc[3][1]);
        }

        const int rowbase = n0 + it * P2_TROWS + (wid << 3);
#pragma unroll
        for (int rp = 0; rp < 4; ++rp) {
            float2 lo = make_float2(acc[rp][0].x, acc[rp][1].x);
            float2 hi = make_float2(acc[rp][0].y, acc[rp][1].y);
            *(float2*)(Ob + (size_t)(rowbase + (rp << 1)) * DD + (lane << 1))     = lo;
            *(float2*)(Ob + (size_t)(rowbase + (rp << 1) + 1) * DD + (lane << 1)) = hi;
        }
    }
}

// ============================ launch ============================
extern "C" void kernel_launch(void* const* d_in, const int* in_sizes, int n_in,
                              void* d_out, int out_size) {
    (void)in_sizes; (void)n_in; (void)out_size;
    const float* q = (const float*)d_in[0];
    const float* k = (const float*)d_in[1];
    const float* v = (const float*)d_in[2];
    float* out = (float*)d_out;

    const int P1_SMEM = (2 * P1_TROWS * KST + 8 * DD * SST) * (int)sizeof(float);
    cudaFuncSetAttribute(ctx_kernel, cudaFuncAttributeMaxDynamicSharedMemorySize, P1_SMEM);

    zero_ctx_kernel<<<(BB * DD * DD + 255) / 256, 256>>>();
    ctx_kernel<<<dim3(P1_CHUNKS, BB), 256, P1_SMEM>>>(k, v);
    out_kernel<<<dim3(P2_CHUNKS, BB), 256>>>(q, out);
}

// round 2
// speedup vs baseline: 1.0011x; 1.0011x over previous
#include <cuda_runtime.h>

#define BB 32
#define NN 16384
#define DD 64

// ---------------- pass 1 (ctx = softmax(k)^T @ v) ----------------
#define P1_CHUNKS 16
#define P1_CROWS (NN / P1_CHUNKS)    // 1024 rows per block
#define P1_TROWS 32                  // rows per smem tile
#define P1_NT (P1_CROWS / P1_TROWS)  // 32 tiles
#define KST 68                       // padded tile row stride (floats, 16B-mult)
#define SST 68                       // stage row stride

// ---------------- pass 2 (out = softmax(q) @ ctx) ----------------
#define P2_CHUNKS 16
#define P2_CROWS (NN / P2_CHUNKS)    // 1024 rows per block
#define P2_TROWS 64                  // rows per tile
#define P2_NT (P2_CROWS / P2_TROWS)  // 16 tiles
#define QST 68                       // qt row stride (floats)

__device__ float g_ctx[BB * DD * DD];   // 512 KB scratch

// packed fp32x2 FMA (2x fp32 throughput vs scalar FFMA on sm_103a)
__device__ __forceinline__ float2 ffma2(float2 a, float2 b, float2 c) {
    union U { float2 f; unsigned long long u; };
    U A, B2, C, R;
    A.f = a; B2.f = b; C.f = c;
    asm("fma.rn.f32x2 %0, %1, %2, %3;"
        : "=l"(R.u) : "l"(A.u), "l"(B2.u), "l"(C.u));
    return R.f;
}

// softmax over 8 local values replicated across an 8-lane group (lanes share row)
__device__ __forceinline__ void softmax8(float4 a, float4 b, float* o) {
    float m = fmaxf(fmaxf(fmaxf(a.x, a.y), fmaxf(a.z, a.w)),
                    fmaxf(fmaxf(b.x, b.y), fmaxf(b.z, b.w)));
    m = fmaxf(m, __shfl_xor_sync(0xffffffffu, m, 1));
    m = fmaxf(m, __shfl_xor_sync(0xffffffffu, m, 2));
    m = fmaxf(m, __shfl_xor_sync(0xffffffffu, m, 4));
    o[0] = __expf(a.x - m); o[1] = __expf(a.y - m);
    o[2] = __expf(a.z - m); o[3] = __expf(a.w - m);
    o[4] = __expf(b.x - m); o[5] = __expf(b.y - m);
    o[6] = __expf(b.z - m); o[7] = __expf(b.w - m);
    float s = o[0] + o[1] + o[2] + o[3] + o[4] + o[5] + o[6] + o[7];
    s += __shfl_xor_sync(0xffffffffu, s, 1);
    s += __shfl_xor_sync(0xffffffffu, s, 2);
    s += __shfl_xor_sync(0xffffffffu, s, 4);
    float inv = __frcp_rn(s);
#pragma unroll
    for (int i = 0; i < 8; i++) o[i] *= inv;
}

__global__ void zero_ctx_kernel() {
    int i = blockIdx.x * blockDim.x + threadIdx.x;
    if (i < BB * DD * DD) g_ctx[i] = 0.f;
}

// ============================ PASS 1 ============================
// grid (P1_CHUNKS, BB), 256 threads. Each warp owns the full 64x64 ctx
// as an 8x16 per-lane register tile, over its subset of rows.
__global__ void __launch_bounds__(256, 1) ctx_kernel(
    const float* __restrict__ K, const float* __restrict__ V)
{
    extern __shared__ float sm[];
    float* kn    = sm;                         // [P1_TROWS][KST]  softmaxed k
    float* vv    = sm + P1_TROWS * KST;        // [P1_TROWS][KST]  raw v
    float* stage = vv + P1_TROWS * KST;        // [8][DD][SST]     warp partials

    const int b  = blockIdx.y;
    const int n0 = blockIdx.x * P1_CROWS;

    const int tid  = threadIdx.x;
    const int wid  = tid >> 5;
    const int lane = tid & 31;

    // load/softmax mapping: 8 lanes per row, 4 rows per warp
    const int lrow = lane >> 3;          // 0..3
    const int lcol = (lane & 7) << 3;    // 0,8,...,56

    // accumulate mapping: lane -> (d-octet, e-16-group)
    const int ti = lane >> 2;            // 0..7  -> d = 8*ti ..
    const int tj = lane & 3;             // 0..3  -> e = 16*tj ..

    const float* Kb = K + ((size_t)b * NN) * DD;
    const float* Vb = V + ((size_t)b * NN) * DD;

    float2 acc[8][8];
#pragma unroll
    for (int i = 0; i < 8; i++)
#pragma unroll
        for (int j = 0; j < 8; j++) acc[i][j] = make_float2(0.f, 0.f);

    // prefetch tile 0
    const float* kp = Kb + (size_t)(n0 + (wid << 2) + lrow) * DD + lcol;
    const float* vp = Vb + (size_t)(n0 + (wid << 2) + lrow) * DD + lcol;
    float4 k0 = *(const float4*)kp;
    float4 k1 = *(const float4*)(kp + 4);
    float4 v0 = *(const float4*)vp;
    float4 v1 = *(const float4*)(vp + 4);

    for (int it = 0; it < P1_NT; ++it) {
        // softmax k segment in registers, store tile to smem
        float o[8];
        softmax8(k0, k1, o);
        const int srow = (wid << 2) + lrow;
        float* kd = kn + srow * KST + lcol;
        ((float4*)kd)[0] = make_float4(o[0], o[1], o[2], o[3]);
        ((float4*)kd)[1] = make_float4(o[4], o[5], o[6], o[7]);
        float* vd = vv + srow * KST + lcol;
        ((float4*)vd)[0] = v0;
        ((float4*)vd)[1] = v1;
        __syncthreads();

        // prefetch next tile (overlaps FMA phase below)
        if (it + 1 < P1_NT) {
            const float* kp2 = Kb + (size_t)(n0 + (it + 1) * P1_TROWS + (wid << 2) + lrow) * DD + lcol;
            const float* vp2 = Vb + (size_t)(n0 + (it + 1) * P1_TROWS + (wid << 2) + lrow) * DD + lcol;
            k0 = *(const float4*)kp2;
            k1 = *(const float4*)(kp2 + 4);
            v0 = *(const float4*)vp2;
            v1 = *(const float4*)(vp2 + 4);
        }

        // accumulate: warp w handles rows {w, w+8, w+16, w+24}
#pragma unroll
        for (int rr = 0; rr < 4; ++rr) {
            const int r = wid + (rr << 3);
            const float* kr = kn + r * KST + (ti << 3);
            const float* vr = vv + r * KST + (tj << 4);
            float4 ka  = ((const float4*)kr)[0];
            float4 kb4 = ((const float4*)kr)[1];
            float4 va  = ((const float4*)vr)[0];
            float4 vb4 = ((const float4*)vr)[1];
            float4 vc  = ((const float4*)vr)[2];
            float4 vd4 = ((const float4*)vr)[3];
            float kk[8] = {ka.x, ka.y, ka.z, ka.w, kb4.x, kb4.y, kb4.z, kb4.w};
            float2 vv2[8] = {
                make_float2(va.x, va.y),  make_float2(va.z, va.w),
                make_float2(vb4.x, vb4.y), make_float2(vb4.z, vb4.w),
                make_float2(vc.x, vc.y),  make_float2(vc.z, vc.w),
                make_float2(vd4.x, vd4.y), make_float2(vd4.z, vd4.w)};
#pragma unroll
            for (int i = 0; i < 8; i++) {
                float2 kd2 = make_float2(kk[i], kk[i]);
#pragma unroll
                for (int j = 0; j < 8; j++)
                    acc[i][j] = ffma2(kd2, vv2[j], acc[i][j]);
            }
        }
        __syncthreads();
    }

    // stage warp partials to smem
    float* st = stage + wid * (DD * SST);
#pragma unroll
    for (int i = 0; i < 8; i++) {
        const int d = (ti << 3) + i;
#pragma unroll
        for (int j = 0; j < 8; j++) {
            const int e = (tj << 4) + (j << 1);
            *(float2*)(st + d * SST + e) = acc[i][j];
        }
    }
    __syncthreads();

    // reduce 8 partials -> atomicAdd into g_ctx
    const int d  = tid >> 2;
    const int e0 = (tid & 3) << 4;
    float4 r0 = make_float4(0, 0, 0, 0), r1 = r0, r2 = r0, r3 = r0;
#pragma unroll
    for (int w = 0; w < 8; w++) {
        const float4* p = (const float4*)(stage + (w * DD + d) * SST + e0);
        float4 a0 = p[0], a1 = p[1], a2 = p[2], a3 = p[3];
        r0.x += a0.x; r0.y += a0.y; r0.z += a0.z; r0.w += a0.w;
        r1.x += a1.x; r1.y += a1.y; r1.z += a1.z; r1.w += a1.w;
        r2.x += a2.x; r2.y += a2.y; r2.z += a2.z; r2.w += a2.w;
        r3.x += a3.x; r3.y += a3.y; r3.z += a3.z; r3.w += a3.w;
    }
    float* dst = g_ctx + b * DD * DD + d * DD + e0;
    atomicAdd(dst + 0,  r0.x); atomicAdd(dst + 1,  r0.y);
    atomicAdd(dst + 2,  r0.z); atomicAdd(dst + 3,  r0.w);
    atomicAdd(dst + 4,  r1.x); atomicAdd(dst + 5,  r1.y);
    atomicAdd(dst + 6,  r1.z); atomicAdd(dst + 7,  r1.w);
    atomicAdd(dst + 8,  r2.x); atomicAdd(dst + 9,  r2.y);
    atomicAdd(dst + 10, r2.z); atomicAdd(dst + 11, r2.w);
    atomicAdd(dst + 12, r3.x); atomicAdd(dst + 13, r3.y);
    atomicAdd(dst + 14, r3.z); atomicAdd(dst + 15, r3.w);
}

// ============================ PASS 2 ============================
// grid (P2_CHUNKS, BB), 256 threads. ctx in smem; q softmaxed in regs,
// stored transposed qt[d][row] so the d-loop is shuffle-free float4 reads.
__global__ void __launch_bounds__(256, 2) out_kernel(
    const float* __restrict__ Q, float* __restrict__ OUT)
{
    __shared__ float sctx[DD * DD];       // [d][e]
    __shared__ float qt[DD][QST];         // [d][row(64)+pad]

    const int b  = blockIdx.y;
    const int n0 = blockIdx.x * P2_CROWS;

    const int tid  = threadIdx.x;
    const int wid  = tid >> 5;
    const int lane = tid & 31;
    const int lrow = lane >> 3;
    const int lcol = (lane & 7) << 3;

    const float* Qb = Q + ((size_t)b * NN) * DD;
    float* Ob       = OUT + ((size_t)b * NN) * DD;

    {   // load ctx (visible after first __syncthreads below)
        const float4* src = (const float4*)(g_ctx + b * DD * DD);
        float4* dst = (float4*)sctx;
        for (int i = tid; i < (DD * DD) / 4; i += 256) dst[i] = src[i];
    }

    // prefetch tile 0: each warp loads 8 rows (two 4-row sub-batches)
    const float* qp0 = Qb + (size_t)(n0 + (wid << 3) + lrow) * DD + lcol;
    float4 qa0 = *(const float4*)qp0;
    float4 qb0 = *(const float4*)(qp0 + 4);
    float4 qa1 = *(const float4*)(qp0 + 4 * DD);
    float4 qb1 = *(const float4*)(qp0 + 4 * DD + 4);

    for (int it = 0; it < P2_NT; ++it) {
        __syncthreads();  // prev-iter FMA reads of qt done (no-op cost at it=0)

        float o[8];
        const int srow = (wid << 3) + lrow;
        softmax8(qa0, qb0, o);
#pragma unroll
        for (int i = 0; i < 8; i++) qt[lcol + i][srow] = o[i];
        softmax8(qa1, qb1, o);
#pragma unroll
        for (int i = 0; i < 8; i++) qt[lcol + i][srow + 4] = o[i];
        __syncthreads();

        // prefetch next tile (overlaps FMA phase)
        if (it + 1 < P2_NT) {
            const float* qp = Qb + (size_t)(n0 + (it + 1) * P2_TROWS + (wid << 3) + lrow) * DD + lcol;
            qa0 = *(const float4*)qp;
            qb0 = *(const float4*)(qp + 4);
            qa1 = *(const float4*)(qp + 4 * DD);
            qb1 = *(const float4*)(qp + 4 * DD + 4);
        }

        // warp 'wid' computes rows [8*wid, 8*wid+8) x all 64 e; lane owns e={2*lane,2*lane+1}
        float2 acc[4][2];
#pragma unroll
        for (int rp = 0; rp < 4; rp++) {
            acc[rp][0] = make_float2(0.f, 0.f);
            acc[rp][1] = make_float2(0.f, 0.f);
        }

        const float* qbase = &qt[0][wid << 3];
        const float* cbase = sctx + (lane << 1);
#pragma unroll 16
        for (int d = 0; d < DD; ++d) {
            float4 qA = *(const float4*)(qbase + d * QST);
            float4 qB = *(const float4*)(qbase + d * QST + 4);
            float2 c  = *(const float2*)(cbase + d * DD);
            float2 cx = make_float2(c.x, c.x);
            float2 cy = make_float2(c.y, c.y);
            float2 q01 = make_float2(qA.x, qA.y);
            float2 q23 = make_float2(qA.z, qA.w);
            float2 q45 = make_float2(qB.x, qB.y);
            float2 q67 = make_float2(qB.z, qB.w);
            acc[0][0] = ffma2(q01, cx, acc[0][0]);
            acc[0][1] = ffma2(q01, cy, acc[0][1]);
            acc[1][0] = ffma2(q23, cx, acc[1][0]);
            acc[1][1] = ffma2(q23, cy, acc[1][1]);
            acc[2][0] = ffma2(q45, cx, acc[2][0]);
            acc[2][1] = ffma2(q45, cy, acc[2][1]);
            acc[3][0] = ffma2(q67, cx, acc[3][0]);
            acc[3][1] = ffma2(q67, cy, acc[3][1]);
        }

        const int rowbase = n0 + it * P2_TROWS + (wid << 3);
#pragma unroll
        for (int rp = 0; rp < 4; ++rp) {
            float2 lo = make_float2(acc[rp][0].x, acc[rp][1].x);
            float2 hi = make_float2(acc[rp][0].y, acc[rp][1].y);
            *(float2*)(Ob + (size_t)(rowbase + (rp << 1)) * DD + (lane << 1))     = lo;
            *(float2*)(Ob + (size_t)(rowbase + (rp << 1) + 1) * DD + (lane << 1)) = hi;
        }
    }
}

// ============================ launch ============================
extern "C" void kernel_launch(void* const* d_in, const int* in_sizes, int n_in,
                              void* d_out, int out_size) {
    (void)in_sizes; (void)n_in; (void)out_size;
    const float* q = (const float*)d_in[0];
    const float* k = (const float*)d_in[1];
    const float* v = (const float*)d_in[2];
    float* out = (float*)d_out;

    const int P1_SMEM = (2 * P1_TROWS * KST + 8 * DD * SST) * (int)sizeof(float);
    cudaFuncSetAttribute(ctx_kernel, cudaFuncAttributeMaxDynamicSharedMemorySize, P1_SMEM);

    zero_ctx_kernel<<<(BB * DD * DD + 255) / 256, 256>>>();
    ctx_kernel<<<dim3(P1_CHUNKS, BB), 256, P1_SMEM>>>(k, v);
    out_kernel<<<dim3(P2_CHUNKS, BB), 256>>>(q, out);
}